// round 8
// baseline (speedup 1.0000x reference)
#include <cuda_runtime.h>
#include <cstdint>

namespace {
constexpr int Bc = 8, Sc = 1024, Dc = 64, BH = 128;
constexpr int TQ = 16, NT = 256;
constexpr int SQ_P = 68;
constexpr int SS_P = 1028;
constexpr int SMEM_FLOATS = TQ * SS_P + TQ * SQ_P;   // 17536 fl = 70144 B
constexpr size_t ATTN_OFF = (size_t)BH * Sc * Dc;
}

// Scratch: fragment-packed tf32 K and V, bit-packed mask.
__device__ float    KF[(size_t)BH * Sc * Dc];          // 33.5 MB
__device__ float    VF[(size_t)BH * Sc * Dc];          // 33.5 MB
__device__ unsigned MBITS[(size_t)Bc * Sc * (Sc / 32)]; // 1 MB

__device__ __forceinline__ float to_tf32(float x) {
    uint32_t u;
    asm("cvt.rna.tf32.f32 %0, %1;" : "=r"(u) : "f"(x));
    return __uint_as_float(u);
}

__device__ __forceinline__ void mma8(float c[4],
                                     float a0, float a1, float a2, float a3,
                                     float b0, float b1) {
    asm volatile(
        "mma.sync.aligned.m16n8k8.row.col.f32.tf32.tf32.f32 "
        "{%0,%1,%2,%3}, {%4,%5,%6,%7}, {%8,%9}, {%0,%1,%2,%3};\n"
        : "+f"(c[0]), "+f"(c[1]), "+f"(c[2]), "+f"(c[3])
        : "r"(__float_as_uint(a0)), "r"(__float_as_uint(a1)),
          "r"(__float_as_uint(a2)), "r"(__float_as_uint(a3)),
          "r"(__float_as_uint(b0)), "r"(__float_as_uint(b1)));
}

// ---- pack K: blocks of 8 n-rows x 8 d-cols; pair idx=g*4+t -> (K[g][t], K[g][t+4])
__global__ void pack_k_kernel(const float* __restrict__ K) {
    __shared__ float t[8][65];
    int blk = blockIdx.x;
    int i = threadIdx.x;
    float4 v = reinterpret_cast<const float4*>(K + (size_t)blk * 512)[i];
    int row = i >> 4, c4 = (i & 15) * 4;
    t[row][c4 + 0] = to_tf32(v.x);  t[row][c4 + 1] = to_tf32(v.y);
    t[row][c4 + 2] = to_tf32(v.z);  t[row][c4 + 3] = to_tf32(v.w);
    __syncthreads();
    float* dst = KF + (size_t)blk * 512;
#pragma unroll
    for (int j = 0; j < 2; j++) {
        int o = i + j * 128;
        int dblk = o >> 5, idx = o & 31, g = idx >> 2, tt = idx & 3;
        float2 p = make_float2(t[g][dblk * 8 + tt], t[g][dblk * 8 + tt + 4]);
        reinterpret_cast<float2*>(dst + dblk * 64)[idx] = p;
    }
}

// ---- pack V: blocks of 8 k-rows x 8 d-cols; pair idx=g*4+t -> (V[t][g], V[t+4][g])
__global__ void pack_v_kernel(const float* __restrict__ V) {
    __shared__ float t[8][65];
    int blk = blockIdx.x;
    int i = threadIdx.x;
    float4 v = reinterpret_cast<const float4*>(V + (size_t)blk * 512)[i];
    int row = i >> 4, c4 = (i & 15) * 4;
    t[row][c4 + 0] = to_tf32(v.x);  t[row][c4 + 1] = to_tf32(v.y);
    t[row][c4 + 2] = to_tf32(v.z);  t[row][c4 + 3] = to_tf32(v.w);
    __syncthreads();
    float* dst = VF + (size_t)blk * 512;
#pragma unroll
    for (int j = 0; j < 2; j++) {
        int o = i + j * 128;
        int dblk = o >> 5, idx = o & 31, g = idx >> 2, tt = idx & 3;
        float2 p = make_float2(t[tt][dblk * 8 + g], t[tt + 4][dblk * 8 + g]);
        reinterpret_cast<float2*>(dst + dblk * 64)[idx] = p;
    }
}

// ---- mask -> bits
__global__ void mask_bits_kernel(const int* __restrict__ M) {
    size_t i = (size_t)blockIdx.x * 256 + threadIdx.x;
    unsigned bal = __ballot_sync(0xffffffffu, M[i] != 0);
    if ((threadIdx.x & 31) == 0) MBITS[i >> 5] = bal;
}

__global__ void __launch_bounds__(NT, 2)
attn_tf32_kernel(const float* __restrict__ Qg_, float* __restrict__ out)
{
    extern __shared__ float sm[];
    float* sS = sm;                       // [TQ][SS_P]
    float* sQ = sS + TQ * SS_P;           // [TQ][SQ_P]; reused as reduction buf

    const int qt = blockIdx.x, bh = blockIdx.y, b = bh >> 4;
    const int tid = threadIdx.x, warp = tid >> 5, lane = tid & 31;
    const int gid = lane >> 2, tig = lane & 3, w8 = warp << 3;

    const float* Qg = Qg_ + ((size_t)bh * Sc + (size_t)qt * TQ) * Dc;
    float* outO = out + ((size_t)bh * Sc + (size_t)qt * TQ) * Dc;
    float* outA = out + ATTN_OFF + ((size_t)bh * Sc + (size_t)qt * TQ) * Sc;

    {   // Q tile -> smem, *1/8, tf32
        int row = tid >> 4, c4 = tid & 15;
        float4 v = reinterpret_cast<const float4*>(Qg)[tid];
        float* dst = sQ + row * SQ_P + c4 * 4;
        dst[0] = to_tf32(v.x * 0.125f); dst[1] = to_tf32(v.y * 0.125f);
        dst[2] = to_tf32(v.z * 0.125f); dst[3] = to_tf32(v.w * 0.125f);
    }
    __syncthreads();

    // A fragments (Q)
    float aq[8][4];
#pragma unroll
    for (int ks = 0; ks < 8; ks++) {
        const float* p = sQ + gid * SQ_P + ks * 8 + tig;
        aq[ks][0] = p[0];   aq[ks][1] = p[8 * SQ_P];
        aq[ks][2] = p[4];   aq[ks][3] = p[8 * SQ_P + 4];
    }

    // ---------------- GEMM1: 4 independent mma chains per tile --------------
    {
        const float2* kfw = reinterpret_cast<const float2*>(
            KF + ((size_t)bh * 128 + warp) * 512) + lane;
        float2 bf[2][8];
#pragma unroll
        for (int ks = 0; ks < 8; ks++)
            bf[0][ks] = __ldg(kfw + ks * 32);

        for (int kt = 0; kt < 16; kt++) {
            int cur = kt & 1;
            if (kt < 15) {
                const float2* nx = kfw + (size_t)(kt + 1) * 2048;
#pragma unroll
                for (int ks = 0; ks < 8; ks++)
                    bf[cur ^ 1][ks] = __ldg(nx + ks * 32);
            }
            float c4s[4][4];
#pragma unroll
            for (int j = 0; j < 4; j++) {
                c4s[j][0] = 0.f; c4s[j][1] = 0.f;
                c4s[j][2] = 0.f; c4s[j][3] = 0.f;
            }
#pragma unroll
            for (int ks = 0; ks < 8; ks++)
                mma8(c4s[ks & 3], aq[ks][0], aq[ks][1], aq[ks][2], aq[ks][3],
                     bf[cur][ks].x, bf[cur][ks].y);

            int col = kt * 64 + w8 + tig * 2;
            float* p  = sS + gid * SS_P + col;
            float* p2 = p + 8 * SS_P;
            p[0]  = (c4s[0][0] + c4s[1][0]) + (c4s[2][0] + c4s[3][0]);
            p[1]  = (c4s[0][1] + c4s[1][1]) + (c4s[2][1] + c4s[3][1]);
            p2[0] = (c4s[0][2] + c4s[1][2]) + (c4s[2][2] + c4s[3][2]);
            p2[1] = (c4s[0][3] + c4s[1][3]) + (c4s[2][3] + c4s[3][3]);
        }
    }
    __syncthreads();

    // ---------------- softmax + bitmask + attn write -------------------------
#pragma unroll
    for (int rr = 0; rr < 2; rr++) {
        int row = warp * 2 + rr;
        float4* srow4 = reinterpret_cast<float4*>(sS + row * SS_P);
        unsigned mw = MBITS[((size_t)(b * Sc + qt * TQ + row)) * 32 + lane];

        float4 v[8];
        float mx = -3.0e38f;
#pragma unroll
        for (int i = 0; i < 8; i++) {
            v[i] = srow4[lane + i * 32];
            mx = fmaxf(mx, fmaxf(fmaxf(v[i].x, v[i].y), fmaxf(v[i].z, v[i].w)));
        }
#pragma unroll
        for (int o = 16; o > 0; o >>= 1)
            mx = fmaxf(mx, __shfl_xor_sync(0xffffffffu, mx, o));

        float sum = 0.f;
#pragma unroll
        for (int i = 0; i < 8; i++) {
            v[i].x = __expf(v[i].x - mx); v[i].y = __expf(v[i].y - mx);
            v[i].z = __expf(v[i].z - mx); v[i].w = __expf(v[i].w - mx);
            sum += (v[i].x + v[i].y) + (v[i].z + v[i].w);
        }
#pragma unroll
        for (int o = 16; o > 0; o >>= 1)
            sum += __shfl_xor_sync(0xffffffffu, sum, o);
        float inv = 1.0f / sum;

        float4* arow = reinterpret_cast<float4*>(outA + (size_t)row * Sc);
#pragma unroll
        for (int i = 0; i < 8; i++) {
            int idx = lane + i * 32;
            unsigned wd  = __shfl_sync(0xffffffffu, mw, (lane >> 3) + 4 * i);
            unsigned nib = wd >> ((lane & 7) * 4);
            float4 w;
            w.x = (nib & 1u) ? v[i].x * inv : -100000.0f;
            w.y = (nib & 2u) ? v[i].y * inv : -100000.0f;
            w.z = (nib & 4u) ? v[i].z * inv : -100000.0f;
            w.w = (nib & 8u) ? v[i].w * inv : -100000.0f;
            __stcs(&arow[idx], w);
            float4 t;
            t.x = to_tf32(w.x); t.y = to_tf32(w.y);
            t.z = to_tf32(w.z); t.w = to_tf32(w.w);
            srow4[idx] = t;
        }
    }
    __syncthreads();

    // ---------------- GEMM2: hybrid split, 4 independent chains --------------
    const int half = warp >> 2, w4 = warp & 3;
    float c2[2][2][4];
#pragma unroll
    for (int nb = 0; nb < 2; nb++)
#pragma unroll
        for (int pr = 0; pr < 2; pr++) {
            c2[nb][pr][0] = 0.f; c2[nb][pr][1] = 0.f;
            c2[nb][pr][2] = 0.f; c2[nb][pr][3] = 0.f;
        }
    {
        const float2* vfb = reinterpret_cast<const float2*>(
            VF + (size_t)bh * 65536 + (size_t)half * 8 * 4096) + lane;
        float2 bv[2][4][2];
        auto ldchunk = [&](int q, float2 dst[4][2]) {
            int it_ = q >> 1, c_ = q & 1;
            const float2* base = vfb + (size_t)it_ * 2048 + c_ * 4 * 256;
#pragma unroll
            for (int k4 = 0; k4 < 4; k4++)
#pragma unroll
                for (int nb = 0; nb < 2; nb++)
                    dst[k4][nb] = __ldg(base + k4 * 256 + (w4 * 2 + nb) * 32);
        };
        ldchunk(0, bv[0]);
        for (int q = 0; q < 16; q++) {
            int cur = q & 1;
            if (q < 15) ldchunk(q + 1, bv[cur ^ 1]);
            int it = q >> 1, c = q & 1;
            int vt = half * 8 + it;
#pragma unroll
            for (int k4 = 0; k4 < 4; k4++) {
                int ks = c * 4 + k4;
                const float* ap = sS + gid * SS_P + vt * 64 + ks * 8 + tig;
                float a0 = ap[0],  a1 = ap[8 * SS_P];
                float a2 = ap[4],  a3 = ap[8 * SS_P + 4];
#pragma unroll
                for (int nb = 0; nb < 2; nb++)
                    mma8(c2[nb][k4 & 1], a0, a1, a2, a3,
                         bv[cur][k4][nb].x, bv[cur][k4][nb].y);
            }
        }
    }
    __syncthreads();      // all reads of sS attn done

    // ---------------- combine halves (reuse sQ) ------------------------------
    float* sR = sQ;
    if (half == 1) {
#pragma unroll
        for (int nb = 0; nb < 2; nb++) {
            int dcol = w4 * 16 + nb * 8 + tig * 2;
            *reinterpret_cast<float2*>(sR + gid * SQ_P + dcol) =
                make_float2(c2[nb][0][0] + c2[nb][1][0],
                            c2[nb][0][1] + c2[nb][1][1]);
            *reinterpret_cast<float2*>(sR + (gid + 8) * SQ_P + dcol) =
                make_float2(c2[nb][0][2] + c2[nb][1][2],
                            c2[nb][0][3] + c2[nb][1][3]);
        }
    }
    __syncthreads();
    if (half == 0) {
#pragma unroll
        for (int nb = 0; nb < 2; nb++) {
            int dcol = w4 * 16 + nb * 8 + tig * 2;
            float2 o0 = *reinterpret_cast<const float2*>(sR + gid * SQ_P + dcol);
            float2 o1 = *reinterpret_cast<const float2*>(sR + (gid + 8) * SQ_P + dcol);
            *reinterpret_cast<float2*>(outO + gid * Dc + dcol) =
                make_float2(c2[nb][0][0] + c2[nb][1][0] + o0.x,
                            c2[nb][0][1] + c2[nb][1][1] + o0.y);
            *reinterpret_cast<float2*>(outO + (gid + 8) * Dc + dcol) =
                make_float2(c2[nb][0][2] + c2[nb][1][2] + o1.x,
                            c2[nb][0][3] + c2[nb][1][3] + o1.y);
        }
    }
}

extern "C" void kernel_launch(void* const* d_in, const int* in_sizes, int n_in,
                              void* d_out, int out_size)
{
    (void)in_sizes; (void)n_in; (void)out_size;
    const float* Q = (const float*)d_in[0];
    const float* K = (const float*)d_in[1];
    const float* V = (const float*)d_in[2];
    const int*   M = (const int*)d_in[3];
    float* out = (float*)d_out;

    pack_k_kernel<<<BH * 128, 128>>>(K);
    pack_v_kernel<<<BH * 128, 128>>>(V);
    mask_bits_kernel<<<(Bc * Sc * Sc) / 256, 256>>>(M);

    cudaFuncSetAttribute(attn_tf32_kernel,
                         cudaFuncAttributeMaxDynamicSharedMemorySize,
                         SMEM_FLOATS * (int)sizeof(float));
    dim3 grid(Sc / TQ, BH);
    attn_tf32_kernel<<<grid, NT, SMEM_FLOATS * sizeof(float)>>>(Q, out);
}

// round 9
// speedup vs baseline: 1.7444x; 1.7444x over previous
#include <cuda_runtime.h>
#include <cuda_fp16.h>
#include <cstdint>

namespace {
constexpr int Bc = 8, Sc = 1024, Dc = 64, BH = 128;
constexpr int TQ = 16, NT = 256;
constexpr int SQ_P = 68;
constexpr int SS_P = 1028;
constexpr int SMEM_FLOATS = TQ * SS_P + TQ * SQ_P;   // 17536 fl = 70144 B
constexpr size_t ATTN_OFF = (size_t)BH * Sc * Dc;
constexpr int PP = 68;            // partial-reduction row pitch
}

// Scratch: fragment-packed fp16 K and V, bit-packed mask.
__device__ uint2    KF2[(size_t)BH * 16384];            // 16.7 MB
__device__ uint2    VF2[(size_t)BH * 16384];            // 16.7 MB
__device__ unsigned MBITS[(size_t)Bc * Sc * (Sc / 32)]; // 1 MB

__device__ __forceinline__ float to_tf32(float x) {
    uint32_t u;
    asm("cvt.rna.tf32.f32 %0, %1;" : "=r"(u) : "f"(x));
    return __uint_as_float(u);
}

__device__ __forceinline__ uint32_t h2u(__half2 h) {
    return *reinterpret_cast<uint32_t*>(&h);
}

__device__ __forceinline__ void mma16(float c[4],
                                      uint32_t a0, uint32_t a1,
                                      uint32_t a2, uint32_t a3,
                                      uint32_t b0, uint32_t b1) {
    asm volatile(
        "mma.sync.aligned.m16n8k16.row.col.f32.f16.f16.f32 "
        "{%0,%1,%2,%3}, {%4,%5,%6,%7}, {%8,%9}, {%0,%1,%2,%3};\n"
        : "+f"(c[0]), "+f"(c[1]), "+f"(c[2]), "+f"(c[3])
        : "r"(a0), "r"(a1), "r"(a2), "r"(a3), "r"(b0), "r"(b1));
}

// ---- pack K -> fp16 B-fragments: block (8n x 16k); lane(g,t):
//      lo = {K[n0+g][k0+2t], +1}, hi = {K[n0+g][k0+2t+8], +9}
__global__ void pack_k_kernel(const float* __restrict__ K) {
    __shared__ __half h[64][72];
    int blk = blockIdx.x;                  // bh*16 + kt
    int tid = threadIdx.x;
    const float4* src = reinterpret_cast<const float4*>(K + (size_t)blk * 4096);
#pragma unroll
    for (int j = 0; j < 4; j++) {
        int i = tid + j * 256;             // 0..1023
        int row = i >> 4, c4 = (i & 15) * 4;
        float4 v = src[i];
        h[row][c4 + 0] = __float2half_rn(v.x);
        h[row][c4 + 1] = __float2half_rn(v.y);
        h[row][c4 + 2] = __float2half_rn(v.z);
        h[row][c4 + 3] = __float2half_rn(v.w);
    }
    __syncthreads();
    uint2* dst = KF2 + (size_t)blk * 1024;
#pragma unroll
    for (int j = 0; j < 4; j++) {
        int o = tid + j * 256;             // 0..1023
        int nb = o >> 7, rem = o & 127, ks = rem >> 5, l = rem & 31;
        int g = l >> 2, t = l & 3;
        int n = nb * 8 + g, k0 = ks * 16 + 2 * t;
        __half2 lo = __halves2half2(h[n][k0],     h[n][k0 + 1]);
        __half2 hi = __halves2half2(h[n][k0 + 8], h[n][k0 + 9]);
        dst[o] = make_uint2(h2u(lo), h2u(hi));
    }
}

// ---- pack V -> fp16 B-fragments: block (16k x 8d); lane(g,t):
//      lo = {V[k0+2t][d0+g], V[k0+2t+1][d0+g]}, hi = {+8, +9}
__global__ void pack_v_kernel(const float* __restrict__ V) {
    __shared__ __half h[64][72];           // row = k local, col = d
    int blk = blockIdx.x;                  // bh*16 + kc (64-k chunk)
    int tid = threadIdx.x;
    const float4* src = reinterpret_cast<const float4*>(V + (size_t)blk * 4096);
#pragma unroll
    for (int j = 0; j < 4; j++) {
        int i = tid + j * 256;
        int row = i >> 4, c4 = (i & 15) * 4;
        float4 v = src[i];
        h[row][c4 + 0] = __float2half_rn(v.x);
        h[row][c4 + 1] = __float2half_rn(v.y);
        h[row][c4 + 2] = __float2half_rn(v.z);
        h[row][c4 + 3] = __float2half_rn(v.w);
    }
    __syncthreads();
    uint2* dst = VF2 + (size_t)blk * 1024;
#pragma unroll
    for (int j = 0; j < 4; j++) {
        int o = tid + j * 256;
        int ksl = o >> 8, rem = o & 255, db = rem >> 5, l = rem & 31;
        int g = l >> 2, t = l & 3;
        int k0 = ksl * 16 + 2 * t, d = db * 8 + g;
        __half2 lo = __halves2half2(h[k0][d],     h[k0 + 1][d]);
        __half2 hi = __halves2half2(h[k0 + 8][d], h[k0 + 9][d]);
        dst[o] = make_uint2(h2u(lo), h2u(hi));
    }
}

// ---- mask -> bits
__global__ void mask_bits_kernel(const int* __restrict__ M) {
    size_t i = (size_t)blockIdx.x * 256 + threadIdx.x;
    unsigned bal = __ballot_sync(0xffffffffu, M[i] != 0);
    if ((threadIdx.x & 31) == 0) MBITS[i >> 5] = bal;
}

__global__ void __launch_bounds__(NT, 2)
attn_f16_kernel(const float* __restrict__ Qg_, float* __restrict__ out)
{
    extern __shared__ float sm[];
    float* sS = sm;                       // [TQ][SS_P]; fp32 scores -> fp16 attn -> partials
    float* sQ = sS + TQ * SS_P;           // [TQ][SQ_P]

    const int qt = blockIdx.x, bh = blockIdx.y, b = bh >> 4;
    const int tid = threadIdx.x, warp = tid >> 5, lane = tid & 31;
    const int gid = lane >> 2, tig = lane & 3, w8 = warp << 3;

    const float* Qg = Qg_ + ((size_t)bh * Sc + (size_t)qt * TQ) * Dc;
    float* outO = out + ((size_t)bh * Sc + (size_t)qt * TQ) * Dc;
    float* outA = out + ATTN_OFF + ((size_t)bh * Sc + (size_t)qt * TQ) * Sc;

    {   // Q tile -> smem, *1/8 (fp32; converted to fp16 at frag build)
        int row = tid >> 4, c4 = tid & 15;
        float4 v = reinterpret_cast<const float4*>(Qg)[tid];
        float* dst = sQ + row * SQ_P + c4 * 4;
        dst[0] = v.x * 0.125f; dst[1] = v.y * 0.125f;
        dst[2] = v.z * 0.125f; dst[3] = v.w * 0.125f;
    }
    __syncthreads();

    // A fragments (Q/8) as fp16, 4 k16-steps
    uint32_t aq[4][4];
#pragma unroll
    for (int ks = 0; ks < 4; ks++) {
        const float* p0 = sQ + gid * SQ_P + ks * 16 + tig * 2;
        const float* p1 = p0 + 8 * SQ_P;
        float2 f0 = *reinterpret_cast<const float2*>(p0);
        float2 f1 = *reinterpret_cast<const float2*>(p1);
        float2 f2 = *reinterpret_cast<const float2*>(p0 + 8);
        float2 f3 = *reinterpret_cast<const float2*>(p1 + 8);
        aq[ks][0] = h2u(__floats2half2_rn(f0.x, f0.y));
        aq[ks][1] = h2u(__floats2half2_rn(f1.x, f1.y));
        aq[ks][2] = h2u(__floats2half2_rn(f2.x, f2.y));
        aq[ks][3] = h2u(__floats2half2_rn(f3.x, f3.y));
    }

    // ---------------- GEMM1: scores = (Q/8) @ K^T (fp16 mma) ----------------
    {
        const uint2* kf = KF2 + (size_t)bh * 16384 + warp * 128 + lane;
        uint2 bf[2][4];
#pragma unroll
        for (int ks = 0; ks < 4; ks++)
            bf[0][ks] = __ldg(kf + ks * 32);

        for (int kt = 0; kt < 16; kt++) {
            int cur = kt & 1;
            if (kt < 15) {
                const uint2* nx = kf + (size_t)(kt + 1) * 1024;
#pragma unroll
                for (int ks = 0; ks < 4; ks++)
                    bf[cur ^ 1][ks] = __ldg(nx + ks * 32);
            }
            float cA[4] = {0,0,0,0}, cB[4] = {0,0,0,0};
            mma16(cA, aq[0][0], aq[0][1], aq[0][2], aq[0][3],
                  bf[cur][0].x, bf[cur][0].y);
            mma16(cB, aq[1][0], aq[1][1], aq[1][2], aq[1][3],
                  bf[cur][1].x, bf[cur][1].y);
            mma16(cA, aq[2][0], aq[2][1], aq[2][2], aq[2][3],
                  bf[cur][2].x, bf[cur][2].y);
            mma16(cB, aq[3][0], aq[3][1], aq[3][2], aq[3][3],
                  bf[cur][3].x, bf[cur][3].y);

            int col = kt * 64 + w8 + tig * 2;
            float* p  = sS + gid * SS_P + col;
            float* p2 = p + 8 * SS_P;
            p[0]  = cA[0] + cB[0]; p[1]  = cA[1] + cB[1];
            p2[0] = cA[2] + cB[2]; p2[1] = cA[3] + cB[3];
        }
    }
    __syncthreads();

    // ------- softmax + bitmask; write fp32 attn to gmem, fp16 attn/2 to smem --
#pragma unroll
    for (int rr = 0; rr < 2; rr++) {
        int row = warp * 2 + rr;
        float* srow = sS + row * SS_P;
        float4* srow4 = reinterpret_cast<float4*>(srow);
        unsigned mw = MBITS[((size_t)(b * Sc + qt * TQ + row)) * 32 + lane];

        float4 v[8];
        float mx = -3.0e38f;
#pragma unroll
        for (int i = 0; i < 8; i++) {
            v[i] = srow4[lane + i * 32];
            mx = fmaxf(mx, fmaxf(fmaxf(v[i].x, v[i].y), fmaxf(v[i].z, v[i].w)));
        }
#pragma unroll
        for (int o = 16; o > 0; o >>= 1)
            mx = fmaxf(mx, __shfl_xor_sync(0xffffffffu, mx, o));

        float sum = 0.f;
#pragma unroll
        for (int i = 0; i < 8; i++) {
            v[i].x = __expf(v[i].x - mx); v[i].y = __expf(v[i].y - mx);
            v[i].z = __expf(v[i].z - mx); v[i].w = __expf(v[i].w - mx);
            sum += (v[i].x + v[i].y) + (v[i].z + v[i].w);
        }
#pragma unroll
        for (int o = 16; o > 0; o >>= 1)
            sum += __shfl_xor_sync(0xffffffffu, sum, o);
        float inv = 1.0f / sum;

        float4* arow = reinterpret_cast<float4*>(outA + (size_t)row * Sc);
#pragma unroll
        for (int i = 0; i < 8; i++) {
            int idx = lane + i * 32;
            unsigned wd  = __shfl_sync(0xffffffffu, mw, (lane >> 3) + 4 * i);
            unsigned nib = wd >> ((lane & 7) * 4);
            float4 w;
            w.x = (nib & 1u) ? v[i].x * inv : -100000.0f;
            w.y = (nib & 2u) ? v[i].y * inv : -100000.0f;
            w.z = (nib & 4u) ? v[i].z * inv : -100000.0f;
            w.w = (nib & 8u) ? v[i].w * inv : -100000.0f;
            __stcs(&arow[idx], w);                 // exact fp32 attn
            uint2 hh = make_uint2(
                h2u(__floats2half2_rn(w.x * 0.5f, w.y * 0.5f)),
                h2u(__floats2half2_rn(w.z * 0.5f, w.w * 0.5f)));
            *reinterpret_cast<uint2*>(srow + idx * 2) = hh;   // fp16 attn/2
        }
    }
    __syncthreads();

    // ------- GEMM2: out = 2 * (attn/2 @ V), full 8-way k-split ---------------
    // warp owns k in [warp*128, warp*128+128) = 8 k16-steps; all 64 d-cols.
    float c2[8][4];
#pragma unroll
    for (int db = 0; db < 8; db++) {
        c2[db][0] = 0.f; c2[db][1] = 0.f; c2[db][2] = 0.f; c2[db][3] = 0.f;
    }
    {
        const uint2* vfw = VF2 + (size_t)bh * 16384 + (size_t)warp * 2048 + lane;
        uint2 bv[2][8];
#pragma unroll
        for (int db = 0; db < 8; db++)
            bv[0][db] = __ldg(vfw + db * 32);

        for (int s = 0; s < 8; s++) {
            int cur = s & 1;
            if (s < 7) {
                const uint2* nx = vfw + (s + 1) * 256;
#pragma unroll
                for (int db = 0; db < 8; db++)
                    bv[cur ^ 1][db] = __ldg(nx + db * 32);
            }
            // A frags: fp16 attn/2 at half-index warp*128 + s*16 + ...
            int fo = warp * 64 + s * 8 + tig;     // float-offset of half-pair
            uint32_t a0 = *reinterpret_cast<const uint32_t*>(sS + gid * SS_P + fo);
            uint32_t a1 = *reinterpret_cast<const uint32_t*>(sS + (gid + 8) * SS_P + fo);
            uint32_t a2 = *reinterpret_cast<const uint32_t*>(sS + gid * SS_P + fo + 4);
            uint32_t a3 = *reinterpret_cast<const uint32_t*>(sS + (gid + 8) * SS_P + fo + 4);
#pragma unroll
            for (int db = 0; db < 8; db++)
                mma16(c2[db], a0, a1, a2, a3, bv[cur][db].x, bv[cur][db].y);
        }
    }
    __syncthreads();      // all reads of sS fp16 attn done

    // ---------------- 8-way partial reduction (reuse sS) ---------------------
    {
        float* sP = sS;   // [8 warps][16 rows][PP]
#pragma unroll
        for (int db = 0; db < 8; db++) {
            int dcol = db * 8 + tig * 2;
            *reinterpret_cast<float2*>(sP + warp * (TQ * PP) + gid * PP + dcol) =
                make_float2(c2[db][0], c2[db][1]);
            *reinterpret_cast<float2*>(sP + warp * (TQ * PP) + (gid + 8) * PP + dcol) =
                make_float2(c2[db][2], c2[db][3]);
        }
        __syncthreads();

        int r  = tid >> 4;          // 0..15
        int cc = (tid & 15) * 4;    // 0..60
        float4 acc = make_float4(0.f, 0.f, 0.f, 0.f);
#pragma unroll
        for (int w = 0; w < 8; w++) {
            float4 v = *reinterpret_cast<const float4*>(
                sP + w * (TQ * PP) + r * PP + cc);
            acc.x += v.x; acc.y += v.y; acc.z += v.z; acc.w += v.w;
        }
        acc.x *= 2.f; acc.y *= 2.f; acc.z *= 2.f; acc.w *= 2.f;   // undo /2
        *reinterpret_cast<float4*>(outO + r * Dc + cc) = acc;
    }
}

extern "C" void kernel_launch(void* const* d_in, const int* in_sizes, int n_in,
                              void* d_out, int out_size)
{
    (void)in_sizes; (void)n_in; (void)out_size;
    const float* Q = (const float*)d_in[0];
    const float* K = (const float*)d_in[1];
    const float* V = (const float*)d_in[2];
    const int*   M = (const int*)d_in[3];
    float* out = (float*)d_out;

    pack_k_kernel<<<BH * 16, 256>>>(K);
    pack_v_kernel<<<BH * 16, 256>>>(V);
    mask_bits_kernel<<<(Bc * Sc * Sc) / 256, 256>>>(M);

    cudaFuncSetAttribute(attn_f16_kernel,
                         cudaFuncAttributeMaxDynamicSharedMemorySize,
                         SMEM_FLOATS * (int)sizeof(float));
    dim3 grid(Sc / TQ, BH);
    attn_f16_kernel<<<grid, NT, SMEM_FLOATS * sizeof(float)>>>(Q, out);
}